// round 3
// baseline (speedup 1.0000x reference)
#include <cuda_runtime.h>
#include <cstdint>

#define N_VERTS 40962
#define N_POOL  10242
#define KNB     7
// C1 = C2 = 64, C3 = 128, IN_CH = 8, B = 8
// h1/h2 layout: [n][c][b]  (512 floats per vertex, b innermost)
// h3 layout:    [(c3*N_POOL + n)*8 + b]  (matches FC flatten order)

__device__ float g_h1[N_VERTS * 512];          // 84 MB
__device__ float g_h2[N_VERTS * 512];          // 84 MB
__device__ float g_h3[128 * N_POOL * 8];       // 42 MB
__device__ int   g_nebs[N_VERTS * KNB];        // normalized int32 indices

// ---------------- f32x2 packed helpers ----------------
__device__ __forceinline__ unsigned long long dup2(float w) {
    unsigned long long r;
    unsigned int u = __float_as_uint(w);
    asm("mov.b64 %0, {%1, %2};" : "=l"(r) : "r"(u), "r"(u));
    return r;
}
__device__ __forceinline__ void ffma2(unsigned long long& a,
                                      unsigned long long w,
                                      unsigned long long g) {
    asm("fma.rn.f32x2 %0, %1, %2, %0;" : "+l"(a) : "l"(w), "l"(g));
}

// ---------------- nebs dtype normalization ----------------
// Reference declares int64, but JAX x64 may be disabled -> int32.
// If int64: the high 32-bit words (odd positions) of the first elements are
// all zero. In the int32 interpretation those are 6 random neighbor indices
// in [0, 40962) -- all-zero probability ~0.
__global__ void convert_nebs_kernel(const unsigned int* __restrict__ raw) {
    int i = blockIdx.x * 256 + threadIdx.x;
    if (i >= N_VERTS * KNB) return;
    bool is64 = ((raw[1] | raw[3] | raw[5] | raw[7] | raw[9] | raw[11]) == 0u);
    int v;
    if (is64) v = (int)((const long long*)raw)[i];
    else      v = ((const int*)raw)[i];
    g_nebs[i] = v;
}

// ---------------- conv1: h1[n][c][b] = relu(W1 @ x + b1) ----------------
__global__ void __launch_bounds__(256) conv1_kernel(
    const float* __restrict__ x, const float* __restrict__ W1,
    const float* __restrict__ b1) {
    __shared__ float xs[64 * 33];   // [j=b*8+ci][v], padded rows
    __shared__ float W1s[512];
    __shared__ float b1s[64];
    const int tid = threadIdx.x;
    const int n0 = blockIdx.x * 32;

    // FIX R3: blockDim is 256 -- must loop to cover all 512 weights.
    for (int p = tid; p < 512; p += 256) W1s[p] = W1[p];
    if (tid < 64)  b1s[tid] = b1[tid];
    for (int p = tid; p < 2048; p += 256) {
        int j = p >> 5, t = p & 31, n = n0 + t;
        xs[j * 33 + t] = (n < N_VERTS) ? x[j * N_VERTS + n] : 0.f;
    }
    __syncthreads();

    for (int p = tid; p < 16384; p += 256) {
        int v = p >> 9, r = p & 511;
        int n = n0 + v;
        if (n >= N_VERTS) break;
        int c = r >> 3, b = r & 7;
        float acc = b1s[c];
#pragma unroll
        for (int ci = 0; ci < 8; ci++)
            acc = fmaf(xs[(b * 8 + ci) * 33 + v], W1s[c * 8 + ci], acc);
        g_h1[n * 512 + r] = fmaxf(acc, 0.f);
    }
}

// ---------------- conv2: gathered 7-tap conv, f32x2 packed ----------------
// Block: 512 threads, 32 vertices. smem: W2s[k][c][o] (114688B) +
// Gs[v][c*8+b] (65536B) + sidx (896B) = 181120 B dynamic.
#define CONV2_SMEM (28672 * 4 + 16384 * 4 + 224 * 4)

__global__ void __launch_bounds__(512, 1) conv2_kernel(
    const float* __restrict__ W2, const float* __restrict__ b2) {
    extern __shared__ float smem[];
    float* W2s = smem;                       // 28672 floats
    float* Gs  = smem + 28672;               // 16384 floats
    int*   sidx = (int*)(smem + 28672 + 16384); // 224 ints

    const int tid = threadIdx.x;
    const int n0 = blockIdx.x * 32;

    // Stage W2 [o][c][k] -> W2s[k][c][o]
    for (int p = tid; p < 28672; p += 512) {
        int o = p / 448;
        int r = p - o * 448;
        int c = r / 7;
        int k = r - c * 7;
        W2s[(k * 64 + c) * 64 + o] = W2[p];
    }
    if (tid < 224) {
        int v = tid / 7;
        int n = n0 + v;
        sidx[tid] = (n < N_VERTS) ? g_nebs[n * 7 + (tid - v * 7)] : 0;
    }

    const int og = tid & 7;          // o = og*8 .. og*8+7
    const int bg = (tid >> 3) & 3;   // b = bg*2, bg*2+1 (packed)
    const int vg = tid >> 5;         // 0..15, v = vg*2, vg*2+1

    unsigned long long acc0[8], acc1[8];
#pragma unroll
    for (int j = 0; j < 8; j++) { acc0[j] = 0ULL; acc1[j] = 0ULL; }

    for (int k = 0; k < 7; k++) {
        __syncthreads();
        // Gather 32 neighbor rows (2KB each) into Gs
        for (int p = tid; p < 4096; p += 512) {
            int v = p >> 7, q = p & 127;
            const float4 val = *reinterpret_cast<const float4*>(
                &g_h1[sidx[v * 7 + k] * 512 + q * 4]);
            *reinterpret_cast<float4*>(&Gs[v * 512 + q * 4]) = val;
        }
        __syncthreads();

        const float* wbase  = &W2s[k * 4096 + og * 8];
        const float* gbaseA = &Gs[(vg * 2) * 512 + bg * 2];
        const float* gbaseB = gbaseA + 512;
#pragma unroll 4
        for (int c = 0; c < 64; c++) {
            const float4 wa = *reinterpret_cast<const float4*>(wbase + c * 64);
            const float4 wb = *reinterpret_cast<const float4*>(wbase + c * 64 + 4);
            const unsigned long long gA =
                *reinterpret_cast<const unsigned long long*>(gbaseA + c * 8);
            const unsigned long long gB =
                *reinterpret_cast<const unsigned long long*>(gbaseB + c * 8);
            unsigned long long w;
            w = dup2(wa.x); ffma2(acc0[0], w, gA); ffma2(acc1[0], w, gB);
            w = dup2(wa.y); ffma2(acc0[1], w, gA); ffma2(acc1[1], w, gB);
            w = dup2(wa.z); ffma2(acc0[2], w, gA); ffma2(acc1[2], w, gB);
            w = dup2(wa.w); ffma2(acc0[3], w, gA); ffma2(acc1[3], w, gB);
            w = dup2(wb.x); ffma2(acc0[4], w, gA); ffma2(acc1[4], w, gB);
            w = dup2(wb.y); ffma2(acc0[5], w, gA); ffma2(acc1[5], w, gB);
            w = dup2(wb.z); ffma2(acc0[6], w, gA); ffma2(acc1[6], w, gB);
            w = dup2(wb.w); ffma2(acc0[7], w, gA); ffma2(acc1[7], w, gB);
        }
    }

    // Epilogue: bias + relu, write h2[n][o][b]
#pragma unroll
    for (int i = 0; i < 2; i++) {
        int n = n0 + vg * 2 + i;
        if (n >= N_VERTS) continue;
        const unsigned long long* acc = i ? acc1 : acc0;
#pragma unroll
        for (int j = 0; j < 8; j++) {
            int o = og * 8 + j;
            float bb = __ldg(&b2[o]);
            float2 r;
            r.x = fmaxf(__uint_as_float((unsigned)acc[j]) + bb, 0.f);
            r.y = fmaxf(__uint_as_float((unsigned)(acc[j] >> 32)) + bb, 0.f);
            *reinterpret_cast<float2*>(&g_h2[n * 512 + o * 8 + bg * 2]) = r;
        }
    }
}

// ---------------- pool (max over 7) + conv3 (1x1, 64->128) ----------------
__global__ void __launch_bounds__(256) pool_conv3_kernel(
    const float* __restrict__ W3, const float* __restrict__ b3) {
    __shared__ float W3s[128 * 65];  // padded rows
    __shared__ float ps[4 * 512];
    __shared__ float b3s[128];
    __shared__ int sidx3[28];
    const int tid = threadIdx.x;
    const int n0 = blockIdx.x * 4;

    for (int p = tid; p < 8192; p += 256) {
        int o = p >> 6, c = p & 63;
        W3s[o * 65 + c] = W3[p];
    }
    if (tid < 128) b3s[tid] = b3[tid];
    if (tid < 28) {
        int v = tid / 7, n = n0 + v;
        sidx3[tid] = (n < N_POOL) ? g_nebs[n * 7 + (tid - v * 7)] : 0;
    }
    __syncthreads();

    // maxpool over 7 neighbor rows of h2
    for (int p = tid; p < 2048; p += 256) {
        int v = p >> 9, r = p & 511;
        float m = -3.4e38f;
#pragma unroll
        for (int k = 0; k < 7; k++)
            m = fmaxf(m, g_h2[sidx3[v * 7 + k] * 512 + r]);
        ps[v * 512 + r] = m;
    }
    __syncthreads();

    // 1x1 conv: thread = (v, o), all 8 batch lanes
    for (int p = tid; p < 512; p += 256) {
        int v = p >> 7, o = p & 127;
        int n = n0 + v;
        if (n >= N_POOL) continue;
        float bb = b3s[o];
        float acc[8];
#pragma unroll
        for (int b = 0; b < 8; b++) acc[b] = bb;
        const float* wrow = &W3s[o * 65];
        const float* prow = &ps[v * 512];
#pragma unroll 8
        for (int c = 0; c < 64; c++) {
            float w = wrow[c];
            float4 pa = *reinterpret_cast<const float4*>(&prow[c * 8]);
            float4 pb = *reinterpret_cast<const float4*>(&prow[c * 8 + 4]);
            acc[0] = fmaf(pa.x, w, acc[0]);
            acc[1] = fmaf(pa.y, w, acc[1]);
            acc[2] = fmaf(pa.z, w, acc[2]);
            acc[3] = fmaf(pa.w, w, acc[3]);
            acc[4] = fmaf(pb.x, w, acc[4]);
            acc[5] = fmaf(pb.y, w, acc[5]);
            acc[6] = fmaf(pb.z, w, acc[6]);
            acc[7] = fmaf(pb.w, w, acc[7]);
        }
        float* dst = &g_h3[(o * N_POOL + n) * 8];
        float4 r0, r1;
        r0.x = fmaxf(acc[0], 0.f); r0.y = fmaxf(acc[1], 0.f);
        r0.z = fmaxf(acc[2], 0.f); r0.w = fmaxf(acc[3], 0.f);
        r1.x = fmaxf(acc[4], 0.f); r1.y = fmaxf(acc[5], 0.f);
        r1.z = fmaxf(acc[6], 0.f); r1.w = fmaxf(acc[7], 0.f);
        *reinterpret_cast<float4*>(dst)     = r0;
        *reinterpret_cast<float4*>(dst + 4) = r1;
    }
}

// ---------------- FC ----------------
__global__ void fc_init_kernel(float* __restrict__ out,
                               const float* __restrict__ bfc) {
    int t = threadIdx.x;
    if (t < 512) out[t] = bfc[t & 63];
}

#define FC_NI (128 * N_POOL)  // 1310976

__global__ void __launch_bounds__(256) fc_kernel(
    const float* __restrict__ Wfc, float* __restrict__ out) {
    const int og = blockIdx.x;          // 8 output groups of 8 channels
    const int nch = gridDim.y;
    const int chunk = blockIdx.y;
    const int i0 = (int)(((long long)FC_NI * chunk) / nch);
    const int i1 = (int)(((long long)FC_NI * (chunk + 1)) / nch);

    float acc[8][8];                     // [j][b]
#pragma unroll
    for (int j = 0; j < 8; j++)
#pragma unroll
        for (int b = 0; b < 8; b++) acc[j][b] = 0.f;

    for (int i = i0 + threadIdx.x; i < i1; i += 256) {
        const float* hp = &g_h3[i * 8];
        const float4 h0 = *reinterpret_cast<const float4*>(hp);
        const float4 h1v = *reinterpret_cast<const float4*>(hp + 4);
        float hv[8] = {h0.x, h0.y, h0.z, h0.w, h1v.x, h1v.y, h1v.z, h1v.w};
#pragma unroll
        for (int j = 0; j < 8; j++) {
            float w = __ldg(&Wfc[(size_t)(og * 8 + j) * FC_NI + i]);
#pragma unroll
            for (int b = 0; b < 8; b++)
                acc[j][b] = fmaf(w, hv[b], acc[j][b]);
        }
    }

    // intra-warp reduce
#pragma unroll
    for (int j = 0; j < 8; j++)
#pragma unroll
        for (int b = 0; b < 8; b++) {
            float v = acc[j][b];
#pragma unroll
            for (int s = 16; s > 0; s >>= 1)
                v += __shfl_xor_sync(0xffffffffu, v, s);
            acc[j][b] = v;
        }

    __shared__ float wred[8][64];
    const int lane = threadIdx.x & 31, warp = threadIdx.x >> 5;
    if (lane == 0) {
#pragma unroll
        for (int j = 0; j < 8; j++)
#pragma unroll
            for (int b = 0; b < 8; b++)
                wred[warp][j * 8 + b] = acc[j][b];
    }
    __syncthreads();
    if (threadIdx.x < 64) {
        int j = threadIdx.x >> 3, b = threadIdx.x & 7;
        float s = 0.f;
#pragma unroll
        for (int w = 0; w < 8; w++) s += wred[w][j * 8 + b];
        atomicAdd(&out[b * 64 + og * 8 + j], s);
    }
}

// ---------------- launch ----------------
extern "C" void kernel_launch(void* const* d_in, const int* in_sizes, int n_in,
                              void* d_out, int out_size) {
    const float* x    = (const float*)d_in[0];
    const void*  nebs = d_in[1];
    const float* W1   = (const float*)d_in[2];
    const float* b1   = (const float*)d_in[3];
    const float* W2   = (const float*)d_in[4];
    const float* b2   = (const float*)d_in[5];
    const float* W3   = (const float*)d_in[6];
    const float* b3   = (const float*)d_in[7];
    const float* Wfc  = (const float*)d_in[8];
    const float* bfc  = (const float*)d_in[9];
    float* out = (float*)d_out;

    cudaFuncSetAttribute(conv2_kernel,
                         cudaFuncAttributeMaxDynamicSharedMemorySize,
                         CONV2_SMEM);

    convert_nebs_kernel<<<(N_VERTS * KNB + 255) / 256, 256>>>(
        (const unsigned int*)nebs);
    conv1_kernel<<<(N_VERTS + 31) / 32, 256>>>(x, W1, b1);
    conv2_kernel<<<(N_VERTS + 31) / 32, 512, CONV2_SMEM>>>(W2, b2);
    pool_conv3_kernel<<<(N_POOL + 3) / 4, 256>>>(W3, b3);
    fc_init_kernel<<<1, 512>>>(out, bfc);
    {
        dim3 grid(8, 96);
        fc_kernel<<<grid, 256>>>(Wfc, out);
    }
}

// round 5
// speedup vs baseline: 2.5035x; 2.5035x over previous
#include <cuda_runtime.h>
#include <cuda_bf16.h>
#include <cstdint>

#define N_VERTS 40962
#define N_POOL  10242

// h1 split bf16, layout [n][b][c] (c innermost, 512 bf16 per vertex = 1KB)
__device__ __nv_bfloat16 g_h1h[N_VERTS * 512];
__device__ __nv_bfloat16 g_h1l[N_VERTS * 512];
__device__ float g_h2[N_VERTS * 512];          // fp32 [n][b][c]
__device__ float g_h3[128 * N_POOL * 8];       // [(o*N_POOL+n)*8+b]
__device__ int   g_nebs[N_VERTS * 7];
__device__ __nv_bfloat16 g_W2h[7 * 64 * 64];   // [k][o][c]
__device__ __nv_bfloat16 g_W2l[7 * 64 * 64];
__device__ __nv_bfloat16 g_W3h[128 * 64];      // [o][c]
__device__ __nv_bfloat16 g_W3l[128 * 64];

// ---------------- helpers ----------------
__device__ __forceinline__ uint32_t smem_u32(const void* p) {
    uint32_t a;
    asm("{ .reg .u64 t; cvta.to.shared.u64 t, %1; cvt.u32.u64 %0, t; }"
        : "=r"(a) : "l"(p));
    return a;
}
__device__ __forceinline__ uint32_t swz(uint32_t off) {
    return off ^ ((off >> 3) & 0x70u);
}
__device__ __forceinline__ void ldsm_x4(uint32_t* r, uint32_t addr) {
    asm volatile(
        "ldmatrix.sync.aligned.m8n8.x4.shared.b16 {%0,%1,%2,%3}, [%4];"
        : "=r"(r[0]), "=r"(r[1]), "=r"(r[2]), "=r"(r[3]) : "r"(addr));
}
__device__ __forceinline__ void mma_bf16(float* d, const uint32_t* a,
                                         const uint32_t* b) {
    asm volatile(
        "mma.sync.aligned.m16n8k16.row.col.f32.bf16.bf16.f32 "
        "{%0,%1,%2,%3}, {%4,%5,%6,%7}, {%8,%9}, {%0,%1,%2,%3};"
        : "+f"(d[0]), "+f"(d[1]), "+f"(d[2]), "+f"(d[3])
        : "r"(a[0]), "r"(a[1]), "r"(a[2]), "r"(a[3]), "r"(b[0]), "r"(b[1]));
}
__device__ __forceinline__ void cp16(uint32_t dst, const void* src) {
    asm volatile("cp.async.cg.shared.global [%0], [%1], 16;"
                 :: "r"(dst), "l"(src) : "memory");
}
#define CP_COMMIT() asm volatile("cp.async.commit_group;" ::: "memory")
#define CP_WAIT(n)  asm volatile("cp.async.wait_group %0;" :: "n"(n) : "memory")

// ---------------- nebs dtype normalization ----------------
__global__ void convert_nebs_kernel(const unsigned int* __restrict__ raw) {
    int i = blockIdx.x * 256 + threadIdx.x;
    if (i >= N_VERTS * 7) return;
    bool is64 = ((raw[1] | raw[3] | raw[5] | raw[7] | raw[9] | raw[11]) == 0u);
    int v;
    if (is64) v = (int)((const long long*)raw)[i];
    else      v = ((const int*)raw)[i];
    g_nebs[i] = v;
}

// ---------------- weight prep: bf16 hi/lo split ----------------
__global__ void prep_w2_kernel(const float* __restrict__ W2) {
    int p = blockIdx.x * 256 + threadIdx.x;
    if (p >= 28672) return;
    int k = p >> 12, r = p & 4095, o = r >> 6, c = r & 63;
    float w = W2[(o * 64 + c) * 7 + k];
    __nv_bfloat16 h = __float2bfloat16(w);
    g_W2h[p] = h;
    g_W2l[p] = __float2bfloat16(w - __bfloat162float(h));
}
__global__ void prep_w3_kernel(const float* __restrict__ W3) {
    int p = blockIdx.x * 256 + threadIdx.x;
    if (p >= 8192) return;
    float w = W3[p];
    __nv_bfloat16 h = __float2bfloat16(w);
    g_W3h[p] = h;
    g_W3l[p] = __float2bfloat16(w - __bfloat162float(h));
}

// ---------------- conv1: fp32, split-store bf16 hi/lo [n][b][c] ----------------
__global__ void __launch_bounds__(256) conv1_kernel(
    const float* __restrict__ x, const float* __restrict__ W1,
    const float* __restrict__ b1) {
    __shared__ float xs[64 * 33];
    __shared__ float W1s[512];
    __shared__ float b1s[64];
    const int tid = threadIdx.x;
    const int n0 = blockIdx.x * 32;

    for (int p = tid; p < 512; p += 256) W1s[p] = W1[p];
    if (tid < 64) b1s[tid] = b1[tid];
    for (int p = tid; p < 2048; p += 256) {
        int j = p >> 5, t = p & 31, n = n0 + t;
        xs[j * 33 + t] = (n < N_VERTS) ? x[j * N_VERTS + n] : 0.f;
    }
    __syncthreads();

    for (int p = tid; p < 16384; p += 256) {
        int v = p >> 9, r = p & 511;
        int n = n0 + v;
        if (n >= N_VERTS) break;
        int b = r >> 6, c = r & 63;
        float acc = b1s[c];
#pragma unroll
        for (int ci = 0; ci < 8; ci++)
            acc = fmaf(xs[(b * 8 + ci) * 33 + v], W1s[c * 8 + ci], acc);
        acc = fmaxf(acc, 0.f);
        __nv_bfloat16 h = __float2bfloat16(acc);
        g_h1h[(size_t)n * 512 + r] = h;
        g_h1l[(size_t)n * 512 + r] = __float2bfloat16(acc - __bfloat162float(h));
    }
}

// ---------------- conv2: mma.sync bf16-split, M=128 N=64 K=448 ----------------
// dsm (128B-aligned): W2hi [0,57344), W2lo [57344,114688),
// A slot s at 114688 + s*32768 (hi 16KB, lo 16KB)
#define C2_DSMEM (180224 + 256)

__device__ __forceinline__ void c2_gather(uint32_t base, const int* sidx,
                                          int k, int slot, int tid) {
    uint32_t abase = base + 114688u + (uint32_t)slot * 32768u;
    for (int p = tid; p < 2048; p += 256) {
        int half = p >= 1024;
        int q = half ? p - 1024 : p;
        int r = q >> 3, c = q & 7;
        int nb = sidx[(r >> 3) * 7 + k];
        const char* src = (const char*)(half ? g_h1l : g_h1h)
                        + (size_t)nb * 1024 + (size_t)(r & 7) * 128
                        + (size_t)c * 16;
        uint32_t dst = abase + (uint32_t)half * 16384u
                     + swz((uint32_t)(r * 128 + c * 16));
        cp16(dst, src);
    }
}

__global__ void __launch_bounds__(256, 1) conv2_mma_kernel(
    const float* __restrict__ b2) {
    extern __shared__ char dsm_raw[];
    __shared__ int sidx[112];
    const int tid = threadIdx.x, lane = tid & 31, wid = tid >> 5;
    const int n0 = blockIdx.x * 16;
    uint32_t raw = smem_u32(dsm_raw);
    uint32_t base = (raw + 127u) & ~127u;

    if (tid < 112) {
        int v = tid / 7, n = n0 + v;
        sidx[tid] = (n < N_VERTS) ? g_nebs[n * 7 + (tid - v * 7)] : 0;
    }
    // W2 hi+lo -> smem via cp.async (group 0)
    for (int p = tid; p < 7168; p += 256) {
        int half = p >= 3584;
        int q = half ? p - 3584 : p;
        uint32_t dst = base + (uint32_t)half * 57344u + swz((uint32_t)q * 16u);
        const char* src = (const char*)(half ? g_W2l : g_W2h) + (size_t)q * 16;
        cp16(dst, src);
    }
    CP_COMMIT();
    __syncthreads();   // sidx visible before gathers

    c2_gather(base, sidx, 0, 0, tid);
    CP_COMMIT();

    float acc[2][4][4];
#pragma unroll
    for (int mt = 0; mt < 2; mt++)
#pragma unroll
        for (int nt = 0; nt < 4; nt++)
#pragma unroll
            for (int e = 0; e < 4; e++) acc[mt][nt][e] = 0.f;

    const int wm = wid >> 1, wn = wid & 1;   // 4 x 2 warp grid
    const int m_base = wm * 32, n_base = wn * 32;

    for (int k = 0; k < 7; k++) {
        const int slot = k & 1;
        if (k < 6) { c2_gather(base, sidx, k + 1, slot ^ 1, tid); CP_COMMIT(); }
        if (k < 6) { CP_WAIT(1); } else { CP_WAIT(0); }
        __syncthreads();

        const uint32_t abase = base + 114688u + (uint32_t)slot * 32768u;
        const uint32_t bbase = base + (uint32_t)k * 8192u;
#pragma unroll
        for (int kc = 0; kc < 4; kc++) {
            uint32_t Ah[2][4], Al[2][4], Bh[2][4], Bl[2][4];
#pragma unroll
            for (int mt = 0; mt < 2; mt++) {
                int row = m_base + mt * 16 + (lane & 15);
                int ch = kc * 2 + (lane >> 4);
                uint32_t off = swz((uint32_t)(row * 128 + ch * 16));
                ldsm_x4(Ah[mt], abase + off);
                ldsm_x4(Al[mt], abase + 16384u + off);
            }
#pragma unroll
            for (int bt = 0; bt < 2; bt++) {
                int row = n_base + bt * 16 + (lane & 7) + ((lane >> 4) << 3);
                int ch = kc * 2 + ((lane >> 3) & 1);
                uint32_t off = swz((uint32_t)(row * 128 + ch * 16));
                ldsm_x4(Bh[bt], bbase + off);
                ldsm_x4(Bl[bt], bbase + 57344u + off);
            }
#pragma unroll
            for (int mt = 0; mt < 2; mt++)
#pragma unroll
                for (int nt = 0; nt < 4; nt++) {
                    const uint32_t* bh = &Bh[nt >> 1][(nt & 1) * 2];
                    const uint32_t* bl = &Bl[nt >> 1][(nt & 1) * 2];
                    mma_bf16(acc[mt][nt], Ah[mt], bh);   // hi*hi
                    mma_bf16(acc[mt][nt], Ah[mt], bl);   // hi*lo
                    mma_bf16(acc[mt][nt], Al[mt], bh);   // lo*hi
                }
        }
        __syncthreads();
    }

    // epilogue: bias + relu -> g_h2 [n][b][c] fp32
#pragma unroll
    for (int mt = 0; mt < 2; mt++) {
        int r0 = m_base + mt * 16 + (lane >> 2);
        int r1 = r0 + 8;
        int nA = n0 + (r0 >> 3), bA = r0 & 7;
        int nB = n0 + (r1 >> 3), bB = r1 & 7;
#pragma unroll
        for (int nt = 0; nt < 4; nt++) {
            int col = n_base + nt * 8 + (lane & 3) * 2;
            float bb0 = __ldg(&b2[col]), bb1 = __ldg(&b2[col + 1]);
            const float* a4 = acc[mt][nt];
            if (nA < N_VERTS) {
                float2 r;
                r.x = fmaxf(a4[0] + bb0, 0.f);
                r.y = fmaxf(a4[1] + bb1, 0.f);
                *(float2*)&g_h2[(size_t)nA * 512 + bA * 64 + col] = r;
            }
            if (nB < N_VERTS) {
                float2 r;
                r.x = fmaxf(a4[2] + bb0, 0.f);
                r.y = fmaxf(a4[3] + bb1, 0.f);
                *(float2*)&g_h2[(size_t)nB * 512 + bB * 64 + col] = r;
            }
        }
    }
}

// ---------------- pool + conv3: fused, mma.sync M=128 N=128 K=64 ----------------
// dsm: W3hi [0,16K), W3lo [16K,32K), Ahi [32K,48K), Alo [48K,64K)
#define P3_DSMEM (65536 + 256)

__global__ void __launch_bounds__(256, 1) pool_conv3_mma_kernel(
    const float* __restrict__ b3) {
    extern __shared__ char dsm_raw[];
    __shared__ int sidx[112];
    const int tid = threadIdx.x, lane = tid & 31, wid = tid >> 5;
    const int n0 = blockIdx.x * 16;
    uint32_t raw = smem_u32(dsm_raw);
    uint32_t base = (raw + 127u) & ~127u;

    if (tid < 112) {
        int v = tid / 7, n = n0 + v;
        sidx[tid] = (n < N_POOL) ? g_nebs[n * 7 + (tid - v * 7)] : 0;
    }
    // W3 hi+lo via cp.async
    for (int p = tid; p < 2048; p += 256) {
        int half = p >= 1024;
        int q = half ? p - 1024 : p;
        uint32_t dst = base + (uint32_t)half * 16384u + swz((uint32_t)q * 16u);
        const char* src = (const char*)(half ? g_W3l : g_W3h) + (size_t)q * 16;
        cp16(dst, src);
    }
    CP_COMMIT();
    __syncthreads();   // sidx

    // pool (max over 7 taps, fp32) + bf16 split -> A smem
    {
        int j = tid >> 1, hc = tid & 1;     // row j = vloc*8+b, half-channels
        int v = j >> 3, b = j & 7;
        float4 m[8];
#pragma unroll
        for (int q = 0; q < 8; q++)
            m[q] = make_float4(-3.4e38f, -3.4e38f, -3.4e38f, -3.4e38f);
        for (int k = 0; k < 7; k++) {
            const float* src =
                &g_h2[(size_t)sidx[v * 7 + k] * 512 + b * 64 + hc * 32];
#pragma unroll
            for (int q = 0; q < 8; q++) {
                float4 t4 = *(const float4*)(src + q * 4);
                m[q].x = fmaxf(m[q].x, t4.x);
                m[q].y = fmaxf(m[q].y, t4.y);
                m[q].z = fmaxf(m[q].z, t4.z);
                m[q].w = fmaxf(m[q].w, t4.w);
            }
        }
        uint32_t hiw[16], low[16];
#pragma unroll
        for (int q = 0; q < 8; q++) {
            float f[4] = {m[q].x, m[q].y, m[q].z, m[q].w};
            __nv_bfloat16 h[4], l[4];
#pragma unroll
            for (int e = 0; e < 4; e++) {
                h[e] = __float2bfloat16(f[e]);
                l[e] = __float2bfloat16(f[e] - __bfloat162float(h[e]));
            }
            __nv_bfloat162 hp0 = {h[0], h[1]}, hp1 = {h[2], h[3]};
            __nv_bfloat162 lp0 = {l[0], l[1]}, lp1 = {l[2], l[3]};
            hiw[q * 2]     = *reinterpret_cast<uint32_t*>(&hp0);
            hiw[q * 2 + 1] = *reinterpret_cast<uint32_t*>(&hp1);
            low[q * 2]     = *reinterpret_cast<uint32_t*>(&lp0);
            low[q * 2 + 1] = *reinterpret_cast<uint32_t*>(&lp1);
        }
#pragma unroll
        for (int i = 0; i < 4; i++) {
            uint32_t off = swz((uint32_t)(j * 128 + hc * 64 + i * 16));
            *(uint4*)(dsm_raw + (base - raw) + 32768u + off) =
                make_uint4(hiw[i * 4], hiw[i * 4 + 1], hiw[i * 4 + 2], hiw[i * 4 + 3]);
            *(uint4*)(dsm_raw + (base - raw) + 49152u + off) =
                make_uint4(low[i * 4], low[i * 4 + 1], low[i * 4 + 2], low[i * 4 + 3]);
        }
    }
    CP_WAIT(0);
    __syncthreads();

    const int wm = wid >> 1, wn = wid & 1;   // 4 x 2 warps, warp = M32 x N64
    const int m_base = wm * 32, n_base = wn * 64;
    float acc[2][8][4];
#pragma unroll
    for (int mt = 0; mt < 2; mt++)
#pragma unroll
        for (int nt = 0; nt < 8; nt++)
#pragma unroll
            for (int e = 0; e < 4; e++) acc[mt][nt][e] = 0.f;

    const uint32_t abase = base + 32768u;
    const uint32_t bbase = base;
#pragma unroll
    for (int kc = 0; kc < 4; kc++) {
        uint32_t Ah[2][4], Al[2][4], Bh[4][4], Bl[4][4];
#pragma unroll
        for (int mt = 0; mt < 2; mt++) {
            int row = m_base + mt * 16 + (lane & 15);
            int ch = kc * 2 + (lane >> 4);
            uint32_t off = swz((uint32_t)(row * 128 + ch * 16));
            ldsm_x4(Ah[mt], abase + off);
            ldsm_x4(Al[mt], abase + 16384u + off);
        }
#pragma unroll
        for (int bt = 0; bt < 4; bt++) {
            int row = n_base + bt * 16 + (lane & 7) + ((lane >> 4) << 3);
            int ch = kc * 2 + ((lane >> 3) & 1);
            uint32_t off = swz((uint32_t)(row * 128 + ch * 16));
            ldsm_x4(Bh[bt], bbase + off);
            ldsm_x4(Bl[bt], bbase + 16384u + off);
        }
#pragma unroll
        for (int mt = 0; mt < 2; mt++)
#pragma unroll
            for (int nt = 0; nt < 8; nt++) {
                const uint32_t* bh = &Bh[nt >> 1][(nt & 1) * 2];
                const uint32_t* bl = &Bl[nt >> 1][(nt & 1) * 2];
                mma_bf16(acc[mt][nt], Ah[mt], bh);
                mma_bf16(acc[mt][nt], Ah[mt], bl);
                mma_bf16(acc[mt][nt], Al[mt], bh);
            }
    }

    // epilogue: bias + relu -> g_h3 [(o*N_POOL+n)*8+b]
#pragma unroll
    for (int mt = 0; mt < 2; mt++) {
        int r0 = m_base + mt * 16 + (lane >> 2);
        int r1 = r0 + 8;
        int v0 = r0 >> 3, b0i = r0 & 7;
        int v1 = r1 >> 3, b1i = r1 & 7;
#pragma unroll
        for (int nt = 0; nt < 8; nt++) {
            int col = n_base + nt * 8 + (lane & 3) * 2;
            float bb0 = __ldg(&b3[col]), bb1 = __ldg(&b3[col + 1]);
            const float* a4 = acc[mt][nt];
            if (n0 + v0 < N_POOL) {
                size_t idx = ((size_t)col * N_POOL + (n0 + v0)) * 8 + b0i;
                g_h3[idx] = fmaxf(a4[0] + bb0, 0.f);
                g_h3[idx + (size_t)N_POOL * 8] = fmaxf(a4[1] + bb1, 0.f);
            }
            if (n0 + v1 < N_POOL) {
                size_t idx = ((size_t)col * N_POOL + (n0 + v1)) * 8 + b1i;
                g_h3[idx] = fmaxf(a4[2] + bb0, 0.f);
                g_h3[idx + (size_t)N_POOL * 8] = fmaxf(a4[3] + bb1, 0.f);
            }
        }
    }
}

// ---------------- FC ----------------
__global__ void fc_init_kernel(float* __restrict__ out,
                               const float* __restrict__ bfc) {
    int t = threadIdx.x;
    if (t < 512) out[t] = bfc[t & 63];
}

#define FC_NI (128 * N_POOL)

__global__ void __launch_bounds__(256) fc_kernel(
    const float* __restrict__ Wfc, float* __restrict__ out) {
    const int og = blockIdx.x;
    const int nch = gridDim.y;
    const int chunk = blockIdx.y;
    const int i0 = (int)(((long long)FC_NI * chunk) / nch);
    const int i1 = (int)(((long long)FC_NI * (chunk + 1)) / nch);

    float acc[8][8];
#pragma unroll
    for (int j = 0; j < 8; j++)
#pragma unroll
        for (int b = 0; b < 8; b++) acc[j][b] = 0.f;

    for (int i = i0 + threadIdx.x; i < i1; i += 256) {
        const float* hp = &g_h3[(size_t)i * 8];
        const float4 h0 = *reinterpret_cast<const float4*>(hp);
        const float4 h1v = *reinterpret_cast<const float4*>(hp + 4);
        float hv[8] = {h0.x, h0.y, h0.z, h0.w, h1v.x, h1v.y, h1v.z, h1v.w};
#pragma unroll
        for (int j = 0; j < 8; j++) {
            float w = __ldg(&Wfc[(size_t)(og * 8 + j) * FC_NI + i]);
#pragma unroll
            for (int b = 0; b < 8; b++)
                acc[j][b] = fmaf(w, hv[b], acc[j][b]);
        }
    }

#pragma unroll
    for (int j = 0; j < 8; j++)
#pragma unroll
        for (int b = 0; b < 8; b++) {
            float v = acc[j][b];
#pragma unroll
            for (int s = 16; s > 0; s >>= 1)
                v += __shfl_xor_sync(0xffffffffu, v, s);
            acc[j][b] = v;
        }

    __shared__ float wred[8][64];
    const int lane = threadIdx.x & 31, warp = threadIdx.x >> 5;
    if (lane == 0) {
#pragma unroll
        for (int j = 0; j < 8; j++)
#pragma unroll
            for (int b = 0; b < 8; b++)
                wred[warp][j * 8 + b] = acc[j][b];
    }
    __syncthreads();
    if (threadIdx.x < 64) {
        int j = threadIdx.x >> 3, b = threadIdx.x & 7;
        float s = 0.f;
#pragma unroll
        for (int w = 0; w < 8; w++) s += wred[w][j * 8 + b];
        atomicAdd(&out[b * 64 + og * 8 + j], s);
    }
}

// ---------------- launch ----------------
extern "C" void kernel_launch(void* const* d_in, const int* in_sizes, int n_in,
                              void* d_out, int out_size) {
    const float* x    = (const float*)d_in[0];
    const void*  nebs = d_in[1];
    const float* W1   = (const float*)d_in[2];
    const float* b1   = (const float*)d_in[3];
    const float* W2   = (const float*)d_in[4];
    const float* b2   = (const float*)d_in[5];
    const float* W3   = (const float*)d_in[6];
    const float* b3   = (const float*)d_in[7];
    const float* Wfc  = (const float*)d_in[8];
    const float* bfc  = (const float*)d_in[9];
    float* out = (float*)d_out;

    cudaFuncSetAttribute(conv2_mma_kernel,
                         cudaFuncAttributeMaxDynamicSharedMemorySize, C2_DSMEM);
    cudaFuncSetAttribute(pool_conv3_mma_kernel,
                         cudaFuncAttributeMaxDynamicSharedMemorySize, P3_DSMEM);

    convert_nebs_kernel<<<(N_VERTS * 7 + 255) / 256, 256>>>(
        (const unsigned int*)nebs);
    prep_w2_kernel<<<(28672 + 255) / 256, 256>>>(W2);
    prep_w3_kernel<<<(8192 + 255) / 256, 256>>>(W3);
    conv1_kernel<<<(N_VERTS + 31) / 32, 256>>>(x, W1, b1);
    conv2_mma_kernel<<<(N_VERTS + 15) / 16, 256, C2_DSMEM>>>(b2);
    pool_conv3_mma_kernel<<<(N_POOL + 15) / 16, 256, P3_DSMEM>>>(b3);
    fc_init_kernel<<<1, 512>>>(out, bfc);
    {
        dim3 grid(8, 96);
        fc_kernel<<<grid, 256>>>(Wfc, out);
    }
}

// round 6
// speedup vs baseline: 2.6514x; 1.0591x over previous
#include <cuda_runtime.h>
#include <cuda_bf16.h>
#include <cstdint>

#define N_VERTS 40962
#define N_POOL  10242

// h1 split bf16, layout [n][b][c] (c innermost, 512 bf16 per vertex = 1KB)
__device__ __nv_bfloat16 g_h1h[N_VERTS * 512];
__device__ __nv_bfloat16 g_h1l[N_VERTS * 512];
__device__ float g_h2[N_VERTS * 512];          // fp32 [n][b][c]
__device__ float g_h3[128 * N_POOL * 8];       // [(o*N_POOL+n)*8+b]
__device__ int   g_nebs[N_VERTS * 7];
__device__ __nv_bfloat16 g_W2h[7 * 64 * 64];   // [k][o][c]
__device__ __nv_bfloat16 g_W2l[7 * 64 * 64];
__device__ __nv_bfloat16 g_W3h[128 * 64];      // [o][c]
__device__ __nv_bfloat16 g_W3l[128 * 64];

// ---------------- helpers ----------------
__device__ __forceinline__ uint32_t smem_u32(const void* p) {
    uint32_t a;
    asm("{ .reg .u64 t; cvta.to.shared.u64 t, %1; cvt.u32.u64 %0, t; }"
        : "=r"(a) : "l"(p));
    return a;
}
__device__ __forceinline__ uint32_t swz(uint32_t off) {
    return off ^ ((off >> 3) & 0x70u);
}
__device__ __forceinline__ void ldsm_x4(uint32_t* r, uint32_t addr) {
    asm volatile(
        "ldmatrix.sync.aligned.m8n8.x4.shared.b16 {%0,%1,%2,%3}, [%4];"
        : "=r"(r[0]), "=r"(r[1]), "=r"(r[2]), "=r"(r[3]) : "r"(addr));
}
__device__ __forceinline__ void mma_bf16(float* d, const uint32_t* a,
                                         const uint32_t* b) {
    asm volatile(
        "mma.sync.aligned.m16n8k16.row.col.f32.bf16.bf16.f32 "
        "{%0,%1,%2,%3}, {%4,%5,%6,%7}, {%8,%9}, {%0,%1,%2,%3};"
        : "+f"(d[0]), "+f"(d[1]), "+f"(d[2]), "+f"(d[3])
        : "r"(a[0]), "r"(a[1]), "r"(a[2]), "r"(a[3]), "r"(b[0]), "r"(b[1]));
}
__device__ __forceinline__ void cp16(uint32_t dst, const void* src) {
    asm volatile("cp.async.cg.shared.global [%0], [%1], 16;"
                 :: "r"(dst), "l"(src) : "memory");
}
#define CP_COMMIT() asm volatile("cp.async.commit_group;" ::: "memory")
#define CP_WAIT(n)  asm volatile("cp.async.wait_group %0;" :: "n"(n) : "memory")

__device__ __forceinline__ uint32_t pack_bf16x2(float a, float b) {
    __nv_bfloat162 p = __floats2bfloat162_rn(a, b);
    return *reinterpret_cast<uint32_t*>(&p);
}

// ---------------- nebs dtype normalization ----------------
__global__ void convert_nebs_kernel(const unsigned int* __restrict__ raw) {
    int i = blockIdx.x * 256 + threadIdx.x;
    if (i >= N_VERTS * 7) return;
    bool is64 = ((raw[1] | raw[3] | raw[5] | raw[7] | raw[9] | raw[11]) == 0u);
    int v;
    if (is64) v = (int)((const long long*)raw)[i];
    else      v = ((const int*)raw)[i];
    g_nebs[i] = v;
}

// ---------------- weight prep: bf16 hi/lo split ----------------
__global__ void prep_w2_kernel(const float* __restrict__ W2) {
    int p = blockIdx.x * 256 + threadIdx.x;
    if (p >= 28672) return;
    int k = p >> 12, r = p & 4095, o = r >> 6, c = r & 63;
    float w = W2[(o * 64 + c) * 7 + k];
    __nv_bfloat16 h = __float2bfloat16(w);
    g_W2h[p] = h;
    g_W2l[p] = __float2bfloat16(w - __bfloat162float(h));
}
__global__ void prep_w3_kernel(const float* __restrict__ W3) {
    int p = blockIdx.x * 256 + threadIdx.x;
    if (p >= 8192) return;
    float w = W3[p];
    __nv_bfloat16 h = __float2bfloat16(w);
    g_W3h[p] = h;
    g_W3l[p] = __float2bfloat16(w - __bfloat162float(h));
}

// ---------------- conv1: thread=(v,q), vectorized split-store ----------------
// h1 layout [n][b][c]; thread computes channels q*8..q*8+7 for all 8 b.
__global__ void __launch_bounds__(256) conv1_kernel(
    const float* __restrict__ x, const float* __restrict__ W1,
    const float* __restrict__ b1) {
    __shared__ float xs[64 * 32];   // [j=b*8+ci][v]
    const int tid = threadIdx.x;
    const int n0 = blockIdx.x * 32;
    const int v = tid >> 3, q = tid & 7;

    for (int p = tid; p < 2048; p += 256) {
        int j = p >> 5, t = p & 31, n = n0 + t;
        xs[p] = (n < N_VERTS) ? x[j * N_VERTS + n] : 0.f;
        (void)t;
    }
    // weights + bias for my 8 channels -> registers
    float wreg[8][8], bb[8];
#pragma unroll
    for (int j = 0; j < 8; j++) {
        float4 wa = *(const float4*)&W1[(q * 8 + j) * 8];
        float4 wb = *(const float4*)&W1[(q * 8 + j) * 8 + 4];
        wreg[j][0] = wa.x; wreg[j][1] = wa.y; wreg[j][2] = wa.z; wreg[j][3] = wa.w;
        wreg[j][4] = wb.x; wreg[j][5] = wb.y; wreg[j][6] = wb.z; wreg[j][7] = wb.w;
        bb[j] = b1[q * 8 + j];
    }
    __syncthreads();

    const int n = n0 + v;
    if (n >= N_VERTS) return;
    uint4* dhi = (uint4*)(g_h1h + (size_t)n * 512);
    uint4* dlo = (uint4*)(g_h1l + (size_t)n * 512);

#pragma unroll
    for (int b = 0; b < 8; b++) {
        float xv[8];
#pragma unroll
        for (int ci = 0; ci < 8; ci++) xv[ci] = xs[(b * 8 + ci) * 32 + v];
        float acc[8];
#pragma unroll
        for (int j = 0; j < 8; j++) {
            float a = bb[j];
#pragma unroll
            for (int ci = 0; ci < 8; ci++) a = fmaf(wreg[j][ci], xv[ci], a);
            acc[j] = fmaxf(a, 0.f);
        }
        uint32_t hiw[4], low[4];
#pragma unroll
        for (int p2 = 0; p2 < 4; p2++) {
            float f0 = acc[p2 * 2], f1 = acc[p2 * 2 + 1];
            __nv_bfloat16 h0 = __float2bfloat16(f0);
            __nv_bfloat16 h1 = __float2bfloat16(f1);
            __nv_bfloat162 hp = {h0, h1};
            hiw[p2] = *reinterpret_cast<uint32_t*>(&hp);
            low[p2] = pack_bf16x2(f0 - __bfloat162float(h0),
                                  f1 - __bfloat162float(h1));
        }
        dhi[b * 8 + q] = make_uint4(hiw[0], hiw[1], hiw[2], hiw[3]);
        dlo[b * 8 + q] = make_uint4(low[0], low[1], low[2], low[3]);
    }
}

// ---------------- conv2: mma.sync bf16-split, M=256 N=64 K=448 ----------------
// smem (128B aligned): W slot w at w*16384 (hi 8K, lo 8K), 2 slots = 32KB
// A slot s at 32768 + s*65536 (hi 32K, lo 32K), 2 slots = 128KB. Total 160KB.
#define C2_DSMEM (163840 + 256)

__device__ __forceinline__ void c2_issue(uint32_t base, const int* sidx,
                                         int k, int slot, int tid) {
    // W2 tap k -> W slot
    uint32_t wbase = base + (uint32_t)slot * 16384u;
    const char* wsh = (const char*)g_W2h + (size_t)k * 8192;
    const char* wsl = (const char*)g_W2l + (size_t)k * 8192;
    for (int p = tid; p < 1024; p += 256) {
        int half = p >= 512;
        int q2 = half ? p - 512 : p;
        cp16(wbase + (uint32_t)half * 8192u + swz((uint32_t)q2 * 16u),
             (half ? wsl : wsh) + (size_t)q2 * 16);
    }
    // A gather: 256 rows x 128B, hi+lo
    uint32_t abase = base + 32768u + (uint32_t)slot * 65536u;
    for (int p = tid; p < 4096; p += 256) {
        int half = p >= 2048;
        int q2 = half ? p - 2048 : p;
        int r = q2 >> 3, c = q2 & 7;
        int nb = sidx[(r >> 3) * 7 + k];
        const char* src = (const char*)(half ? g_h1l : g_h1h)
                        + (size_t)nb * 1024 + (size_t)(r & 7) * 128
                        + (size_t)c * 16;
        cp16(abase + (uint32_t)half * 32768u
                   + swz((uint32_t)(r * 128 + c * 16)), src);
    }
}

__global__ void __launch_bounds__(256, 1) conv2_mma_kernel(
    const float* __restrict__ b2) {
    extern __shared__ char dsm_raw[];
    __shared__ int sidx[224];
    const int tid = threadIdx.x, lane = tid & 31, wid = tid >> 5;
    const int n0 = blockIdx.x * 32;
    uint32_t raw = smem_u32(dsm_raw);
    uint32_t base = (raw + 127u) & ~127u;

    if (tid < 224) {
        int v = tid / 7, n = n0 + v;
        sidx[tid] = (n < N_VERTS) ? g_nebs[n * 7 + (tid - v * 7)] : 0;
    }
    __syncthreads();   // sidx ready

    c2_issue(base, sidx, 0, 0, tid);
    CP_COMMIT();

    float acc[4][4][4];
#pragma unroll
    for (int mt = 0; mt < 4; mt++)
#pragma unroll
        for (int nt = 0; nt < 4; nt++)
#pragma unroll
            for (int e = 0; e < 4; e++) acc[mt][nt][e] = 0.f;

    const int wm = wid >> 1, wn = wid & 1;    // 4 x 2 warps
    const int m_base = wm * 64, n_base = wn * 32;

    for (int k = 0; k < 7; k++) {
        const int slot = k & 1;
        if (k < 6) { c2_issue(base, sidx, k + 1, slot ^ 1, tid); CP_COMMIT(); }
        if (k < 6) { CP_WAIT(1); } else { CP_WAIT(0); }
        __syncthreads();

        const uint32_t wbase = base + (uint32_t)slot * 16384u;
        const uint32_t abase = base + 32768u + (uint32_t)slot * 65536u;
#pragma unroll
        for (int kc = 0; kc < 4; kc++) {
            uint32_t Ah[4][4], Al[4][4], Bh[2][4], Bl[2][4];
#pragma unroll
            for (int mt = 0; mt < 4; mt++) {
                int row = m_base + mt * 16 + (lane & 15);
                int ch = kc * 2 + (lane >> 4);
                uint32_t off = swz((uint32_t)(row * 128 + ch * 16));
                ldsm_x4(Ah[mt], abase + off);
                ldsm_x4(Al[mt], abase + 32768u + off);
            }
#pragma unroll
            for (int bt = 0; bt < 2; bt++) {
                int row = n_base + bt * 16 + (lane & 7) + ((lane >> 4) << 3);
                int ch = kc * 2 + ((lane >> 3) & 1);
                uint32_t off = swz((uint32_t)(row * 128 + ch * 16));
                ldsm_x4(Bh[bt], wbase + off);
                ldsm_x4(Bl[bt], wbase + 8192u + off);
            }
#pragma unroll
            for (int mt = 0; mt < 4; mt++)
#pragma unroll
                for (int nt = 0; nt < 4; nt++) {
                    const uint32_t* bh = &Bh[nt >> 1][(nt & 1) * 2];
                    const uint32_t* bl = &Bl[nt >> 1][(nt & 1) * 2];
                    mma_bf16(acc[mt][nt], Ah[mt], bh);   // hi*hi
                    mma_bf16(acc[mt][nt], Ah[mt], bl);   // hi*lo
                    mma_bf16(acc[mt][nt], Al[mt], bh);   // lo*hi
                }
        }
        __syncthreads();
    }

    // epilogue: bias + relu -> g_h2 [n][b][c] fp32
#pragma unroll
    for (int mt = 0; mt < 4; mt++) {
        int r0 = m_base + mt * 16 + (lane >> 2);
        int r1 = r0 + 8;
        int nA = n0 + (r0 >> 3), bA = r0 & 7;
        int nB = n0 + (r1 >> 3), bB = r1 & 7;
#pragma unroll
        for (int nt = 0; nt < 4; nt++) {
            int col = n_base + nt * 8 + (lane & 3) * 2;
            float bb0 = __ldg(&b2[col]), bb1 = __ldg(&b2[col + 1]);
            const float* a4 = acc[mt][nt];
            if (nA < N_VERTS) {
                float2 r;
                r.x = fmaxf(a4[0] + bb0, 0.f);
                r.y = fmaxf(a4[1] + bb1, 0.f);
                *(float2*)&g_h2[(size_t)nA * 512 + bA * 64 + col] = r;
            }
            if (nB < N_VERTS) {
                float2 r;
                r.x = fmaxf(a4[2] + bb0, 0.f);
                r.y = fmaxf(a4[3] + bb1, 0.f);
                *(float2*)&g_h2[(size_t)nB * 512 + bB * 64 + col] = r;
            }
        }
    }
}

// ---------------- pool + conv3: fused, mma.sync M=128 N=128 K=64 ----------------
// dsm: W3hi [0,16K), W3lo [16K,32K), Ahi [32K,48K), Alo [48K,64K)
#define P3_DSMEM (65536 + 256)

__global__ void __launch_bounds__(256, 1) pool_conv3_mma_kernel(
    const float* __restrict__ b3) {
    extern __shared__ char dsm_raw[];
    __shared__ int sidx[112];
    const int tid = threadIdx.x, lane = tid & 31, wid = tid >> 5;
    const int n0 = blockIdx.x * 16;
    uint32_t raw = smem_u32(dsm_raw);
    uint32_t base = (raw + 127u) & ~127u;

    if (tid < 112) {
        int v = tid / 7, n = n0 + v;
        sidx[tid] = (n < N_POOL) ? g_nebs[n * 7 + (tid - v * 7)] : 0;
    }
    for (int p = tid; p < 2048; p += 256) {
        int half = p >= 1024;
        int q = half ? p - 1024 : p;
        uint32_t dst = base + (uint32_t)half * 16384u + swz((uint32_t)q * 16u);
        const char* src = (const char*)(half ? g_W3l : g_W3h) + (size_t)q * 16;
        cp16(dst, src);
    }
    CP_COMMIT();
    __syncthreads();

    {
        int j = tid >> 1, hc = tid & 1;
        int v = j >> 3, b = j & 7;
        float4 m[8];
#pragma unroll
        for (int q = 0; q < 8; q++)
            m[q] = make_float4(-3.4e38f, -3.4e38f, -3.4e38f, -3.4e38f);
        for (int k = 0; k < 7; k++) {
            const float* src =
                &g_h2[(size_t)sidx[v * 7 + k] * 512 + b * 64 + hc * 32];
#pragma unroll
            for (int q = 0; q < 8; q++) {
                float4 t4 = *(const float4*)(src + q * 4);
                m[q].x = fmaxf(m[q].x, t4.x);
                m[q].y = fmaxf(m[q].y, t4.y);
                m[q].z = fmaxf(m[q].z, t4.z);
                m[q].w = fmaxf(m[q].w, t4.w);
            }
        }
        uint32_t hiw[16], low[16];
#pragma unroll
        for (int q = 0; q < 8; q++) {
            float f[4] = {m[q].x, m[q].y, m[q].z, m[q].w};
            __nv_bfloat16 h[4];
#pragma unroll
            for (int e = 0; e < 4; e++) h[e] = __float2bfloat16(f[e]);
            __nv_bfloat162 hp0 = {h[0], h[1]}, hp1 = {h[2], h[3]};
            hiw[q * 2]     = *reinterpret_cast<uint32_t*>(&hp0);
            hiw[q * 2 + 1] = *reinterpret_cast<uint32_t*>(&hp1);
            low[q * 2]     = pack_bf16x2(f[0] - __bfloat162float(h[0]),
                                         f[1] - __bfloat162float(h[1]));
            low[q * 2 + 1] = pack_bf16x2(f[2] - __bfloat162float(h[2]),
                                         f[3] - __bfloat162float(h[3]));
        }
#pragma unroll
        for (int i = 0; i < 4; i++) {
            uint32_t off = swz((uint32_t)(j * 128 + hc * 64 + i * 16));
            *(uint4*)(dsm_raw + (base - raw) + 32768u + off) =
                make_uint4(hiw[i * 4], hiw[i * 4 + 1], hiw[i * 4 + 2], hiw[i * 4 + 3]);
            *(uint4*)(dsm_raw + (base - raw) + 49152u + off) =
                make_uint4(low[i * 4], low[i * 4 + 1], low[i * 4 + 2], low[i * 4 + 3]);
        }
    }
    CP_WAIT(0);
    __syncthreads();

    const int wm = wid >> 1, wn = wid & 1;
    const int m_base = wm * 32, n_base = wn * 64;
    float acc[2][8][4];
#pragma unroll
    for (int mt = 0; mt < 2; mt++)
#pragma unroll
        for (int nt = 0; nt < 8; nt++)
#pragma unroll
            for (int e = 0; e < 4; e++) acc[mt][nt][e] = 0.f;

    const uint32_t abase = base + 32768u;
    const uint32_t bbase = base;
#pragma unroll
    for (int kc = 0; kc < 4; kc++) {
        uint32_t Ah[2][4], Al[2][4], Bh[4][4], Bl[4][4];
#pragma unroll
        for (int mt = 0; mt < 2; mt++) {
            int row = m_base + mt * 16 + (lane & 15);
            int ch = kc * 2 + (lane >> 4);
            uint32_t off = swz((uint32_t)(row * 128 + ch * 16));
            ldsm_x4(Ah[mt], abase + off);
            ldsm_x4(Al[mt], abase + 16384u + off);
        }
#pragma unroll
        for (int bt = 0; bt < 4; bt++) {
            int row = n_base + bt * 16 + (lane & 7) + ((lane >> 4) << 3);
            int ch = kc * 2 + ((lane >> 3) & 1);
            uint32_t off = swz((uint32_t)(row * 128 + ch * 16));
            ldsm_x4(Bh[bt], bbase + off);
            ldsm_x4(Bl[bt], bbase + 16384u + off);
        }
#pragma unroll
        for (int mt = 0; mt < 2; mt++)
#pragma unroll
            for (int nt = 0; nt < 8; nt++) {
                const uint32_t* bh = &Bh[nt >> 1][(nt & 1) * 2];
                const uint32_t* bl = &Bl[nt >> 1][(nt & 1) * 2];
                mma_bf16(acc[mt][nt], Ah[mt], bh);
                mma_bf16(acc[mt][nt], Ah[mt], bl);
                mma_bf16(acc[mt][nt], Al[mt], bh);
            }
    }

#pragma unroll
    for (int mt = 0; mt < 2; mt++) {
        int r0 = m_base + mt * 16 + (lane >> 2);
        int r1 = r0 + 8;
        int v0 = r0 >> 3, b0i = r0 & 7;
        int v1 = r1 >> 3, b1i = r1 & 7;
#pragma unroll
        for (int nt = 0; nt < 8; nt++) {
            int col = n_base + nt * 8 + (lane & 3) * 2;
            float bb0 = __ldg(&b3[col]), bb1 = __ldg(&b3[col + 1]);
            const float* a4 = acc[mt][nt];
            if (n0 + v0 < N_POOL) {
                size_t idx = ((size_t)col * N_POOL + (n0 + v0)) * 8 + b0i;
                g_h3[idx] = fmaxf(a4[0] + bb0, 0.f);
                g_h3[idx + (size_t)N_POOL * 8] = fmaxf(a4[1] + bb1, 0.f);
            }
            if (n0 + v1 < N_POOL) {
                size_t idx = ((size_t)col * N_POOL + (n0 + v1)) * 8 + b1i;
                g_h3[idx] = fmaxf(a4[2] + bb0, 0.f);
                g_h3[idx + (size_t)N_POOL * 8] = fmaxf(a4[3] + bb1, 0.f);
            }
        }
    }
}

// ---------------- FC ----------------
__global__ void fc_init_kernel(float* __restrict__ out,
                               const float* __restrict__ bfc) {
    int t = threadIdx.x;
    if (t < 512) out[t] = bfc[t & 63];
}

#define FC_NI (128 * N_POOL)

__global__ void __launch_bounds__(256) fc_kernel(
    const float* __restrict__ Wfc, float* __restrict__ out) {
    const int og = blockIdx.x;
    const int nch = gridDim.y;
    const int chunk = blockIdx.y;
    const int i0 = (int)(((long long)FC_NI * chunk) / nch);
    const int i1 = (int)(((long long)FC_NI * (chunk + 1)) / nch);

    float acc[8][8];
#pragma unroll
    for (int j = 0; j < 8; j++)
#pragma unroll
        for (int b = 0; b < 8; b++) acc[j][b] = 0.f;

    for (int i = i0 + threadIdx.x; i < i1; i += 256) {
        const float* hp = &g_h3[(size_t)i * 8];
        const float4 h0 = *reinterpret_cast<const float4*>(hp);
        const float4 h1v = *reinterpret_cast<const float4*>(hp + 4);
        float hv[8] = {h0.x, h0.y, h0.z, h0.w, h1v.x, h1v.y, h1v.z, h1v.w};
#pragma unroll
        for (int j = 0; j < 8; j++) {
            float w = __ldg(&Wfc[(size_t)(og * 8 + j) * FC_NI + i]);
#pragma unroll
            for (int b = 0; b < 8; b++)
                acc[j][b] = fmaf(w, hv[b], acc[j][b]);
        }
    }

#pragma unroll
    for (int j = 0; j < 8; j++)
#pragma unroll
        for (int b = 0; b < 8; b++) {
            float v = acc[j][b];
#pragma unroll
            for (int s = 16; s > 0; s >>= 1)
                v += __shfl_xor_sync(0xffffffffu, v, s);
            acc[j][b] = v;
        }

    __shared__ float wred[8][64];
    const int lane = threadIdx.x & 31, warp = threadIdx.x >> 5;
    if (lane == 0) {
#pragma unroll
        for (int j = 0; j < 8; j++)
#pragma unroll
            for (int b = 0; b < 8; b++)
                wred[warp][j * 8 + b] = acc[j][b];
    }
    __syncthreads();
    if (threadIdx.x < 64) {
        int j = threadIdx.x >> 3, b = threadIdx.x & 7;
        float s = 0.f;
#pragma unroll
        for (int w = 0; w < 8; w++) s += wred[w][j * 8 + b];
        atomicAdd(&out[b * 64 + og * 8 + j], s);
    }
}

// ---------------- launch ----------------
extern "C" void kernel_launch(void* const* d_in, const int* in_sizes, int n_in,
                              void* d_out, int out_size) {
    const float* x    = (const float*)d_in[0];
    const void*  nebs = d_in[1];
    const float* W1   = (const float*)d_in[2];
    const float* b1   = (const float*)d_in[3];
    const float* W2   = (const float*)d_in[4];
    const float* b2   = (const float*)d_in[5];
    const float* W3   = (const float*)d_in[6];
    const float* b3   = (const float*)d_in[7];
    const float* Wfc  = (const float*)d_in[8];
    const float* bfc  = (const float*)d_in[9];
    float* out = (float*)d_out;

    cudaFuncSetAttribute(conv2_mma_kernel,
                         cudaFuncAttributeMaxDynamicSharedMemorySize, C2_DSMEM);
    cudaFuncSetAttribute(pool_conv3_mma_kernel,
                         cudaFuncAttributeMaxDynamicSharedMemorySize, P3_DSMEM);

    convert_nebs_kernel<<<(N_VERTS * 7 + 255) / 256, 256>>>(
        (const unsigned int*)nebs);
    prep_w2_kernel<<<(28672 + 255) / 256, 256>>>(W2);
    prep_w3_kernel<<<(8192 + 255) / 256, 256>>>(W3);
    conv1_kernel<<<(N_VERTS + 31) / 32, 256>>>(x, W1, b1);
    conv2_mma_kernel<<<(N_VERTS + 31) / 32, 256, C2_DSMEM>>>(b2);
    pool_conv3_mma_kernel<<<(N_POOL + 15) / 16, 256, P3_DSMEM>>>(b3);
    fc_init_kernel<<<1, 512>>>(out, bfc);
    {
        dim3 grid(8, 96);
        fc_kernel<<<grid, 256>>>(Wfc, out);
    }
}